// round 3
// baseline (speedup 1.0000x reference)
#include <cuda_runtime.h>
#include <cstdint>

// DropBlock: out = x * block_mask * scale
//   x: (32, 256, 56, 56) fp32, u: (56, 56) fp32
//   GAMMA = 0.1/49 * (56^2 / 50^2)
//   seed = (u < GAMMA); dilated = backward 7x7 max window; bm = 1 - dilated
//   scale = 3136 / sum(bm)

#define H 56
#define W 56
#define HW 3136          // 56*56
#define HW4 784          // HW/4
#define BLOCK 7

// Combined mask*scale LUT, float4-aligned.
__device__ float4 d_ms4[HW4];

// ---------------------------------------------------------------------------
// Kernel 1: one block, computes seed mask, dilation, sum, scale, writes LUT.
// ---------------------------------------------------------------------------
__global__ void __launch_bounds__(1024, 1)
dropblock_mask_kernel(const float* __restrict__ u) {
    __shared__ float seed[HW];
    __shared__ float red[1024];

    const int t = threadIdx.x;
    const float GAMMA = (float)(0.1 * (3136.0 / (49.0 * 2500.0)));

    for (int i = t; i < HW; i += 1024)
        seed[i] = (u[i] < GAMMA) ? 1.0f : 0.0f;
    __syncthreads();

    // Each thread handles up to 4 (h,w) positions; dilated = max over
    // seed[h-6..h][w-6..w] (backward window, matches pad=(6,0)).
    float bm[4];
    int   idx[4];
    int   cnt = 0;
    float local = 0.0f;
    for (int i = t; i < HW; i += 1024) {
        int h = i / W, w = i % W;
        float mx = 0.0f;
        int h0 = h - (BLOCK - 1); if (h0 < 0) h0 = 0;
        int w0 = w - (BLOCK - 1); if (w0 < 0) w0 = 0;
        for (int hh = h0; hh <= h; hh++)
            for (int ww = w0; ww <= w; ww++)
                mx = fmaxf(mx, seed[hh * W + ww]);
        float b = 1.0f - mx;
        bm[cnt] = b; idx[cnt] = i; cnt++;
        local += b;
    }

    red[t] = local;
    __syncthreads();
    #pragma unroll
    for (int s = 512; s > 0; s >>= 1) {
        if (t < s) red[t] += red[t + s];
        __syncthreads();
    }
    float scale = (float)HW / red[0];

    float* ms = (float*)d_ms4;
    for (int c = 0; c < cnt; c++)
        ms[idx[c]] = bm[c] * scale;
}

// ---------------------------------------------------------------------------
// Kernel 2: streaming elementwise multiply, one float4 per thread.
//   n4 = 32*256*56*56/4 = 6,422,528 float4s; mask index = t % 784.
// ---------------------------------------------------------------------------
__global__ void __launch_bounds__(256)
dropblock_apply_kernel(const float4* __restrict__ x, float4* __restrict__ out, int n4) {
    int t = blockIdx.x * blockDim.x + threadIdx.x;
    if (t >= n4) return;
    int hw4 = t % HW4;                 // mul-shift by ptxas (constant divisor)
    float4 m = d_ms4[hw4];             // L1-resident 12.5 KB LUT
    float4 v = __ldg(&x[t]);
    v.x *= m.x; v.y *= m.y; v.z *= m.z; v.w *= m.w;
    // Streaming store: output is never re-read by this kernel chain.
    __stcs(&out[t], v);
}

// ---------------------------------------------------------------------------
extern "C" void kernel_launch(void* const* d_in, const int* in_sizes, int n_in,
                              void* d_out, int out_size) {
    const float* x = (const float*)d_in[0];
    const float* u = (const float*)d_in[1];
    float* out = (float*)d_out;

    dropblock_mask_kernel<<<1, 1024>>>(u);

    const int n4 = out_size / 4;       // 6,422,528
    const int threads = 256;
    const int blocks = (n4 + threads - 1) / threads;
    dropblock_apply_kernel<<<blocks, threads>>>((const float4*)x, (float4*)out, n4);
}